// round 7
// baseline (speedup 1.0000x reference)
#include <cuda_runtime.h>
#include <cuda_fp16.h>
#include <math.h>

#define Ln 6
#define Bt 2
#define Qn 300
#define Dn 256
#define LP1 7

// ---------------- device scratch (no allocs allowed) ----------------
__device__ float g_Aproj[LP1*Bt*Qn*Dn];
__device__ float g_Bproj[LP1*Bt*Qn*Dn];
__device__ float g_gq[LP1*Bt*Qn];
__device__ float g_gk[LP1*Bt*Qn];
// Composite weights: Wc[s][l] = (Wq_or_k[l] | Wsub/obj) @ W1half[s]
__device__ float g_Wc[2*LP1*Dn*Dn];    // 3.5 MB
__device__ float g_bc[2*LP1*Dn];
__device__ float g_wv[2*LP1*Dn];       // composite gate vectors
__device__ float g_gb[2*LP1];          // composite gate bias (bg folded into side 0)
// W2 (256x256) fp16 in mma.m16n8k16 B-fragment order
__device__ uint2 g_W2frag[16*32*32];   // 128 KB

typedef unsigned long long u64;
__device__ __forceinline__ u64 pack2(float x) {
    u64 r; unsigned xi = __float_as_uint(x);
    asm("mov.b64 %0, {%1, %1};" : "=l"(r) : "r"(xi));
    return r;
}
__device__ __forceinline__ u64 fma2(u64 a, u64 b, u64 c) {
    u64 d; asm("fma.rn.f32x2 %0, %1, %2, %3;" : "=l"(d) : "l"(a), "l"(b), "l"(c));
    return d;
}
__device__ __forceinline__ u64 add2(u64 a, u64 b) {
    u64 d; asm("add.rn.f32x2 %0, %1, %2;" : "=l"(d) : "l"(a), "l"(b));
    return d;
}
__device__ __forceinline__ float lo32(u64 v) { return __uint_as_float((unsigned)(v & 0xffffffffull)); }
__device__ __forceinline__ float hi32(u64 v) { return __uint_as_float((unsigned)(v >> 32)); }
__device__ __forceinline__ unsigned smem_u32(const void* p) {
    unsigned a;
    asm("{ .reg .u64 t; cvta.to.shared.u64 t, %1; cvt.u32.u64 %0, t; }" : "=r"(a) : "l"(p));
    return a;
}

// ---------------- small GEMM helper ----------------
template<int ROWS>
__device__ __forceinline__ void gemm_tile(const float* __restrict__ src,
                                          const float* __restrict__ W,
                                          const float* __restrict__ bias,
                                          float* __restrict__ out)
{
    __shared__ float ssrc[ROWS*Dn];
    int tid = threadIdx.x;
    for (int idx = tid; idx < ROWS*Dn/4; idx += 256)
        ((float4*)ssrc)[idx] = ((const float4*)src)[idx];
    __syncthreads();

    int e = tid;
    float acc[ROWS];
    #pragma unroll
    for (int r = 0; r < ROWS; r++) acc[r] = 0.f;

    for (int d = 0; d < Dn; d += 4) {
        float w0 = W[(d+0)*Dn + e];
        float w1 = W[(d+1)*Dn + e];
        float w2 = W[(d+2)*Dn + e];
        float w3 = W[(d+3)*Dn + e];
        #pragma unroll
        for (int r = 0; r < ROWS; r++) {
            float4 s4 = *(const float4*)&ssrc[r*Dn + d];
            acc[r] = fmaf(s4.x, w0, acc[r]);
            acc[r] = fmaf(s4.y, w1, acc[r]);
            acc[r] = fmaf(s4.z, w2, acc[r]);
            acc[r] = fmaf(s4.w, w3, acc[r]);
        }
    }
    float bv = bias ? bias[e] : 0.f;
    #pragma unroll
    for (int r = 0; r < ROWS; r++) out[r*Dn + e] = acc[r] + bv;
}

// ---- composite-weight prep: Wc = Wsrc @ W1half, wv = Wsrc @ wg, bc = b @ W1half ----
__global__ void __launch_bounds__(256)
kernel_prep(const float* __restrict__ Wq,  const float* __restrict__ bq,
            const float* __restrict__ Wk,  const float* __restrict__ bk,
            const float* __restrict__ Wsub,const float* __restrict__ bsub,
            const float* __restrict__ Wobj,const float* __restrict__ bobj,
            const float* __restrict__ Wg,  const float* __restrict__ bg,
            const float* __restrict__ W1)
{
    int tile = blockIdx.x;   // 0..7
    int l    = blockIdx.y;   // 0..6
    int s    = blockIdx.z;   // 0=a(Q), 1=b(K)
    const float* Wsrc = (l < Ln) ? ((s ? Wk : Wq) + (size_t)l*Dn*Dn) : (s ? Wobj : Wsub);
    const float* bsrc = (l < Ln) ? ((s ? bk : bq) + l*Dn) : (s ? bobj : bsub);
    const float* W1s  = W1 + (size_t)s*Dn*Dn;
    const float* wgv  = Wg + s*Dn;
    float* outW = g_Wc + (size_t)(s*LP1 + l)*Dn*Dn;

    gemm_tile<32>(Wsrc + (size_t)tile*32*Dn, W1s, nullptr, outW + (size_t)tile*32*Dn);

    int tid = threadIdx.x;
    if (tid < 32) {
        int row = tile*32 + tid;
        float sd = 0.f;
        for (int m = 0; m < Dn; m++) sd = fmaf(Wsrc[row*Dn + m], wgv[m], sd);
        g_wv[(s*LP1 + l)*Dn + row] = sd;
    }
    if (tile == 0) {
        int e = tid;
        float sd = 0.f;
        for (int d = 0; d < Dn; d++) sd = fmaf(bsrc[d], W1s[d*Dn + e], sd);
        g_bc[(s*LP1 + l)*Dn + e] = sd;
        if (tid == 0) {
            float sg = 0.f;
            for (int d = 0; d < Dn; d++) sg = fmaf(bsrc[d], wgv[d], sg);
            g_gb[s*LP1 + l] = sg + (s == 0 ? bg[0] : 0.f);
        }
    }
}

// ---- A/B projections directly from hs via composite weights ----
__global__ void __launch_bounds__(256)
kernel_proj(const float* __restrict__ hs)
{
    int t = blockIdx.x;          // 0..139 (30-row tiles over 4200)
    int s = blockIdx.y;
    int row0 = t*30;
    int l = row0 / 600;
    int b = (row0 / 300) & 1;
    int q0 = row0 % 300;
    int srcl = (l < Ln) ? l : (Ln - 1);
    const float* src  = hs + ((size_t)(srcl*Bt + b)*Qn + q0)*Dn;
    const float* W    = g_Wc + (size_t)(s*LP1 + l)*Dn*Dn;
    const float* bias = g_bc + (s*LP1 + l)*Dn;
    float* out = (s ? g_Bproj : g_Aproj) + (size_t)row0*Dn;
    gemm_tile<30>(src, W, bias, out);
}

// ---- gate scalars from hs via composite vectors ----
__global__ void kernel_g(const float* __restrict__ hs)
{
    int warp = threadIdx.x >> 5, lane = threadIdx.x & 31;
    int row = blockIdx.x*8 + warp;
    if (row >= LP1*Bt*Qn) return;
    int s = blockIdx.y;
    int l = row / 600;
    int rem = row % 600;
    int b = rem / 300, q = rem % 300;
    int srcl = (l < Ln) ? l : (Ln - 1);
    const float* src = hs + ((size_t)(srcl*Bt + b)*Qn + q)*Dn;
    const float* w   = g_wv + (s*LP1 + l)*Dn;
    float sd = 0.f;
    #pragma unroll
    for (int u = 0; u < 8; u++) sd = fmaf(src[lane + 32*u], w[lane + 32*u], sd);
    #pragma unroll
    for (int off = 16; off > 0; off >>= 1) sd += __shfl_xor_sync(0xffffffffu, sd, off);
    if (lane == 0) {
        float v = sd + g_gb[s*LP1 + l];
        if (s) g_gk[row] = v;
        else   g_gq[row] = v;
    }
}

// ---- W2 fp16 B-fragments ----
__global__ void kernel_prepw2(const float* __restrict__ W2)
{
    int idx = blockIdx.x*256 + threadIdx.x;   // 0..16383
    int lane = idx & 31;
    int gnt  = (idx >> 5) & 31;
    int kt   = idx >> 10;
    int g = lane >> 2, tg = lane & 3;
    int n  = gnt*8 + g;
    int k0 = kt*16 + tg*2;

    unsigned hr[2];
    #pragma unroll
    for (int r = 0; r < 2; r++) {
        int ka = k0 + 8*r;
        __half2 hp;
        hp.x = __float2half(W2[(size_t)ka*Dn + n]);
        hp.y = __float2half(W2[(size_t)(ka+1)*Dn + n]);
        hr[r] = *(unsigned*)&hp;
    }
    uint2 v; v.x = hr[0]; v.y = hr[1];
    g_W2frag[idx] = v;
}

// ---------------- main fused kernel ----------------
#define HS 264
#define SM_GATES 0                  // 7*128*4   = 3584
#define SM_B2    3584               // 1024
#define SM_W3    4608               // 1024
#define SM_HHI   5632               // 128*264*2 = 67584
#define SMEM_TOTAL (5632 + 67584)   // 73216

__device__ __forceinline__ void mma16816(float* c, const unsigned* a,
                                         unsigned b0, unsigned b1)
{
    asm volatile(
        "mma.sync.aligned.m16n8k16.row.col.f32.f16.f16.f32 "
        "{%0,%1,%2,%3}, {%4,%5,%6,%7}, {%8,%9}, {%0,%1,%2,%3};"
        : "+f"(c[0]), "+f"(c[1]), "+f"(c[2]), "+f"(c[3])
        : "r"(a[0]), "r"(a[1]), "r"(a[2]), "r"(a[3]), "r"(b0), "r"(b1));
}

__global__ void __launch_bounds__(256, 2)
kernel_main(const float* __restrict__ b1, const float* __restrict__ b2g,
            const float* __restrict__ W3, const float* __restrict__ b3,
            float* __restrict__ out)
{
    extern __shared__ char smem[];
    float* gates = (float*)(smem + SM_GATES);
    float* b2s   = (float*)(smem + SM_B2);
    float* w3s   = (float*)(smem + SM_W3);
    __half* hhi = (__half*)(smem + SM_HHI);

    int tid = threadIdx.x;
    int wid = tid >> 5, lane = tid & 31;
    int j0 = blockIdx.x*4;
    int i0 = blockIdx.y*32;
    int b  = blockIdx.z;

    b2s[tid] = b2g[tid];
    w3s[tid] = W3[tid];
    for (int t = tid; t < LP1*128; t += 256) {
        int l = t >> 7, p = t & 127;
        int i = min(i0 + (p >> 2), Qn - 1);
        int j = min(j0 + (p & 3),  Qn - 1);
        float z = g_gq[(l*Bt + b)*Qn + i] + g_gk[(l*Bt + b)*Qn + j];
        gates[t] = 1.f / (1.f + expf(-z));
    }
    __syncthreads();

    // ---- phase 1 (f32x2): h1 = relu(sum_l gate*(A_i + B_j) + b1) -> fp16 smem ----
    {
        int half = tid >> 7;             // 0: rows 0-63, 1: rows 64-127
        int e2 = (tid & 127)*2;
        u64 b1p = *(const u64*)&b1[e2];
        #pragma unroll
        for (int gi = 0; gi < 2; gi++) {
            int g4 = half*2 + gi;
            u64 acc[32];
            #pragma unroll
            for (int p = 0; p < 32; p++) acc[p] = 0ull;
            #pragma unroll
            for (int l = 0; l < LP1; l++) {
                const float* Ab = g_Aproj + (size_t)(l*Bt + b)*Qn*Dn;
                const float* Bb = g_Bproj + (size_t)(l*Bt + b)*Qn*Dn;
                u64 av[8], bv[4];
                #pragma unroll
                for (int ii = 0; ii < 8; ii++)
                    av[ii] = *(const u64*)&Ab[(size_t)min(i0 + g4*8 + ii, Qn - 1)*Dn + e2];
                #pragma unroll
                for (int jj = 0; jj < 4; jj++)
                    bv[jj] = *(const u64*)&Bb[(size_t)min(j0 + jj, Qn - 1)*Dn + e2];
                const float* gl = &gates[l*128 + g4*32];
                #pragma unroll
                for (int ii = 0; ii < 8; ii++)
                    #pragma unroll
                    for (int jj = 0; jj < 4; jj++) {
                        int p = ii*4 + jj;
                        acc[p] = fma2(pack2(gl[p]), add2(av[ii], bv[jj]), acc[p]);
                    }
            }
            #pragma unroll
            for (int p = 0; p < 32; p++) {
                u64 v = add2(acc[p], b1p);
                float lo = fmaxf(lo32(v), 0.f);
                float hi = fmaxf(hi32(v), 0.f);
                __half2 hp = __floats2half2_rn(lo, hi);
                *(unsigned*)&hhi[(g4*32 + p)*HS + e2] = *(unsigned*)&hp;
            }
        }
    }
    __syncthreads();

    // ---- phase 2: fp16 HMMA GEMM with ldmatrix A-frags ----
    int g  = lane >> 2;
    int tg = lane & 3;
    int rb = wid * 16;
    float s_g = 0.f, s_g8 = 0.f;

    // ldmatrix lane address: tile t = lane>>3, row r = lane&7
    unsigned hbase = smem_u32(hhi);
    {
        int tt = lane >> 3, r7 = lane & 7;
        int arow = rb + (tt & 1)*8 + r7;
        int acol = (tt >> 1)*8;
        hbase += (unsigned)(arow*HS + acol)*2u;
    }

    #pragma unroll
    for (int nh = 0; nh < 2; nh++) {
        float acc[16][4];
        #pragma unroll
        for (int nt = 0; nt < 16; nt++)
            #pragma unroll
            for (int c = 0; c < 4; c++) acc[nt][c] = 0.f;

        #pragma unroll
        for (int kt = 0; kt < 16; kt++) {
            unsigned af[4];
            asm volatile("ldmatrix.sync.aligned.m8n8.x4.shared.b16 {%0,%1,%2,%3}, [%4];"
                         : "=r"(af[0]), "=r"(af[1]), "=r"(af[2]), "=r"(af[3])
                         : "r"(hbase + (unsigned)kt*32u));

            const uint2* fr = &g_W2frag[((size_t)kt*32 + nh*16)*32 + lane];
            #pragma unroll
            for (int nt = 0; nt < 16; nt++) {
                uint2 bf = fr[nt*32];
                mma16816(acc[nt], af, bf.x, bf.y);
            }
        }

        #pragma unroll
        for (int nt = 0; nt < 16; nt++) {
            int n0 = (nh*16 + nt)*8 + tg*2;
            float w0 = w3s[n0], w1 = w3s[n0+1];
            float c0 = b2s[n0], c1 = b2s[n0+1];
            s_g  = fmaf(fmaxf(acc[nt][0] + c0, 0.f), w0, s_g);
            s_g  = fmaf(fmaxf(acc[nt][1] + c1, 0.f), w1, s_g);
            s_g8 = fmaf(fmaxf(acc[nt][2] + c0, 0.f), w0, s_g8);
            s_g8 = fmaf(fmaxf(acc[nt][3] + c1, 0.f), w1, s_g8);
        }
    }

    #pragma unroll
    for (int off = 1; off <= 2; off <<= 1) {
        s_g  += __shfl_xor_sync(0xffffffffu, s_g,  off);
        s_g8 += __shfl_xor_sync(0xffffffffu, s_g8, off);
    }
    if (tg == 0) {
        float b3v = b3[0];
        int rows[2] = { rb + g, rb + 8 + g };
        float vals[2] = { s_g + b3v, s_g8 + b3v };
        #pragma unroll
        for (int u = 0; u < 2; u++) {
            int p = rows[u];
            int i = i0 + (p >> 2), j = j0 + (p & 3);
            if (i < Qn && j < Qn) {
                #pragma unroll
                for (int lay = 0; lay < Ln; lay++)
                    out[((size_t)(lay*Bt + b)*Qn + i)*Qn + j] = vals[u];
            }
        }
    }
}

extern "C" void kernel_launch(void* const* d_in, const int* in_sizes, int n_in,
                              void* d_out, int out_size)
{
    const float* hs   = (const float*)d_in[0];
    const float* Wq   = (const float*)d_in[1];
    const float* bq   = (const float*)d_in[2];
    const float* Wk   = (const float*)d_in[3];
    const float* bk   = (const float*)d_in[4];
    const float* Wsub = (const float*)d_in[5];
    const float* bsub = (const float*)d_in[6];
    const float* Wobj = (const float*)d_in[7];
    const float* bobj = (const float*)d_in[8];
    const float* Wg   = (const float*)d_in[9];
    const float* bg   = (const float*)d_in[10];
    const float* W1   = (const float*)d_in[11];
    const float* b1   = (const float*)d_in[12];
    const float* W2   = (const float*)d_in[13];
    const float* b2   = (const float*)d_in[14];
    const float* W3   = (const float*)d_in[15];
    const float* b3   = (const float*)d_in[16];
    float* out = (float*)d_out;

    cudaFuncSetAttribute(kernel_main, cudaFuncAttributeMaxDynamicSharedMemorySize, SMEM_TOTAL);

    kernel_prep  <<<dim3(8, 7, 2),   256>>>(Wq, bq, Wk, bk, Wsub, bsub, Wobj, bobj, Wg, bg, W1);
    kernel_proj  <<<dim3(140, 2),    256>>>(hs);
    kernel_g     <<<dim3(525, 2),    256>>>(hs);
    kernel_prepw2<<<64,              256>>>(W2);
    kernel_main  <<<dim3(75, 10, 2), 256, SMEM_TOTAL>>>(b1, b2, W3, b3, out);
}